// round 6
// baseline (speedup 1.0000x reference)
#include <cuda_runtime.h>
#include <cstdint>

#define HIDDEN 2048
#define HEADS 16
#define HEAD_DIM 128
#define BATCH 2
#define SEQ 2048
#define MROWS (BATCH * SEQ)  // 4096

// ---------------- scratch (no allocations allowed) ----------------
__device__ float g_q[MROWS * HIDDEN];     // 32 MB
__device__ float g_k[MROWS * HEAD_DIM];   // 2 MB
__device__ float g_v[MROWS * HEAD_DIM];   // 2 MB
__device__ float g_att[MROWS * HIDDEN];   // 32 MB

__device__ __forceinline__ uint32_t f2tf32(float x) {
    uint32_t r;
    asm("cvt.rna.tf32.f32 %0, %1;" : "=r"(r) : "f"(x));
    return r;
}

#define MMA_TF32(d, a, b)                                                          \
    asm volatile(                                                                  \
        "mma.sync.aligned.m16n8k8.row.col.f32.tf32.tf32.f32 "                      \
        "{%0,%1,%2,%3}, {%4,%5,%6,%7}, {%8,%9}, {%0,%1,%2,%3};"                    \
        : "+f"((d)[0]), "+f"((d)[1]), "+f"((d)[2]), "+f"((d)[3])                   \
        : "r"((a)[0]), "r"((a)[1]), "r"((a)[2]), "r"((a)[3]),                      \
          "r"((b)[0]), "r"((b)[1]))

// ---------------- tf32 mma.sync GEMM: C[M,N] = A[M,K] @ B[N,K]^T ----------------
// 128x128 CTA tile, BK=32, 256 threads (4x2 warps, 32x64 warp tile).
// Smem row stride 36 words: fragment LDS conflict-free, STS.128 at 4-phase floor.
#define BM 128
#define BN 128
#define BK 32
#define SA 36                       // smem row stride in words
#define BUF_WORDS (BM * SA)         // 4608 words per A (or B) buffer
#define G_SMEM (2 * 2 * BUF_WORDS * 4)  // 73728 bytes

__global__ void __launch_bounds__(256) gemm_mma(const float* __restrict__ A,
                                                const float* __restrict__ B,
                                                float* __restrict__ C,
                                                int M, int N, int K) {
    extern __shared__ float sm[];
    const int tid = threadIdx.x;
    const int w = tid >> 5;
    const int lane = tid & 31;
    const int g = lane >> 2;     // 0..7
    const int tg = lane & 3;     // 0..3
    const int warp_m = (w & 3) * 32;
    const int warp_n = (w >> 2) * 64;
    const int m0 = blockIdx.y * BM;
    const int n0 = blockIdx.x * BN;

    float acc[2][8][4];
#pragma unroll
    for (int t = 0; t < 2; t++)
#pragma unroll
        for (int u = 0; u < 8; u++)
#pragma unroll
            for (int j = 0; j < 4; j++) acc[t][u][j] = 0.0f;

    const int steps = K / BK;
    const int r_ld = tid >> 3;           // 0..31 (row group base; +32*i)
    const int c_ld = (tid & 7) * 4;      // word col 0..28

    float4 afr[4], bfr[4];

    auto ldg = [&](int s) {
        const int k0 = s * BK;
#pragma unroll
        for (int i = 0; i < 4; i++) {
            int r = r_ld + i * 32;
            afr[i] = *(const float4*)(A + (size_t)(m0 + r) * K + k0 + c_ld);
            bfr[i] = *(const float4*)(B + (size_t)(n0 + r) * K + k0 + c_ld);
        }
    };
    auto sts = [&](int buf) {
        float* As = sm + buf * (2 * BUF_WORDS);
        float* Bs = As + BUF_WORDS;
#pragma unroll
        for (int i = 0; i < 4; i++) {
            int r = r_ld + i * 32;
            uint4 u;
            u.x = f2tf32(afr[i].x); u.y = f2tf32(afr[i].y);
            u.z = f2tf32(afr[i].z); u.w = f2tf32(afr[i].w);
            *(uint4*)(As + r * SA + c_ld) = u;
            u.x = f2tf32(bfr[i].x); u.y = f2tf32(bfr[i].y);
            u.z = f2tf32(bfr[i].z); u.w = f2tf32(bfr[i].w);
            *(uint4*)(Bs + r * SA + c_ld) = u;
        }
    };
    auto compute = [&](int buf) {
        const uint32_t* As = (const uint32_t*)(sm + buf * (2 * BUF_WORDS));
        const uint32_t* Bs = As + BUF_WORDS;
#pragma unroll
        for (int ks = 0; ks < 4; ks++) {
            const int kc = ks * 8 + tg;
            uint32_t a[2][4];
#pragma unroll
            for (int t = 0; t < 2; t++) {
                int row = warp_m + t * 16 + g;
                a[t][0] = As[row * SA + kc];
                a[t][1] = As[(row + 8) * SA + kc];
                a[t][2] = As[row * SA + kc + 4];
                a[t][3] = As[(row + 8) * SA + kc + 4];
            }
            uint32_t b[8][2];
#pragma unroll
            for (int u = 0; u < 8; u++) {
                int row = warp_n + u * 8 + g;
                b[u][0] = Bs[row * SA + kc];
                b[u][1] = Bs[row * SA + kc + 4];
            }
#pragma unroll
            for (int t = 0; t < 2; t++)
#pragma unroll
                for (int u = 0; u < 8; u++)
                    MMA_TF32(acc[t][u], a[t], b[u]);
        }
    };

    // prologue: stage tile 0
    ldg(0);
    sts(0);
    __syncthreads();

    for (int s = 0; s < steps; s++) {
        const int cur = s & 1;
        if (s + 1 < steps) ldg(s + 1);   // LDG in flight during compute
        compute(cur);
        if (s + 1 < steps) sts(cur ^ 1);
        __syncthreads();
    }

    // epilogue: write C fragments
#pragma unroll
    for (int t = 0; t < 2; t++) {
        int r0 = m0 + warp_m + t * 16 + g;
#pragma unroll
        for (int u = 0; u < 8; u++) {
            int col = n0 + warp_n + u * 8 + 2 * tg;
            float2 v0 = make_float2(acc[t][u][0], acc[t][u][1]);
            float2 v1 = make_float2(acc[t][u][2], acc[t][u][3]);
            *(float2*)(C + (size_t)r0 * N + col) = v0;
            *(float2*)(C + (size_t)(r0 + 8) * N + col) = v1;
        }
    }
}

// ---------------- Flash attention (fp32, unchanged — known good) ----------------
#define TPOS 68

__global__ void __launch_bounds__(256) attn_kernel(const float* __restrict__ Q,
                                                   const float* __restrict__ Km,
                                                   const float* __restrict__ Vm,
                                                   float* __restrict__ O) {
    const int b = blockIdx.z;
    const int h = blockIdx.y;
    const int q0 = blockIdx.x * 64;

    extern __shared__ float sm[];
    float* qs_t = sm;
    float* ks_t = qs_t + 128 * TPOS;
    float* vs   = ks_t + 128 * TPOS;
    float* ss   = vs + 64 * 128;
    float* m_s  = ss + 64 * TPOS;
    float* l_s  = m_s + 64;
    float* f_s  = l_s + 64;

    const int tid = threadIdx.x;
    const int tx = tid & 15;
    const int ty = tid >> 4;
    const int wid = tid >> 5;
    const int lane = tid & 31;
    const float inv_norm = 0.08838834764831845f;

    {
        const float* qbase = Q + (size_t)(b * SEQ + q0) * HIDDEN + h * HEAD_DIM;
#pragma unroll
        for (int it = 0; it < 32; it++) {
            int i = tid + it * 256;
            int r = i >> 7;
            int c = i & 127;
            qs_t[c * TPOS + r] = qbase[(size_t)r * HIDDEN + c];
        }
    }
    if (tid < 64) {
        m_s[tid] = -3.0e38f;
        l_s[tid] = 0.0f;
    }
    __syncthreads();

    float accv[4][8];
#pragma unroll
    for (int i = 0; i < 4; i++)
#pragma unroll
        for (int j = 0; j < 8; j++) accv[i][j] = 0.0f;

    for (int t0 = 0; t0 < SEQ; t0 += 64) {
        {
            const float* kbase = Km + (size_t)(b * SEQ + t0) * HEAD_DIM;
#pragma unroll
            for (int it = 0; it < 32; it++) {
                int i = tid + it * 256;
                int r = i >> 7;
                int c = i & 127;
                ks_t[c * TPOS + r] = kbase[(size_t)r * HEAD_DIM + c];
            }
            const float* vbase = Vm + (size_t)(b * SEQ + t0) * HEAD_DIM;
#pragma unroll
            for (int it = 0; it < 8; it++) {
                int i = tid + it * 256;
                int r = i >> 5;
                int c4 = (i & 31) * 4;
                *(float4*)(vs + r * 128 + c4) = *(const float4*)(vbase + (size_t)r * HEAD_DIM + c4);
            }
        }
        __syncthreads();

        float s[4][4];
#pragma unroll
        for (int i = 0; i < 4; i++)
#pragma unroll
            for (int j = 0; j < 4; j++) s[i][j] = 0.0f;

#pragma unroll 4
        for (int kk = 0; kk < 128; kk++) {
            float4 a = *(const float4*)(qs_t + kk * TPOS + ty * 4);
            float4 bq = *(const float4*)(ks_t + kk * TPOS + tx * 4);
            s[0][0] = fmaf(a.x, bq.x, s[0][0]); s[0][1] = fmaf(a.x, bq.y, s[0][1]);
            s[0][2] = fmaf(a.x, bq.z, s[0][2]); s[0][3] = fmaf(a.x, bq.w, s[0][3]);
            s[1][0] = fmaf(a.y, bq.x, s[1][0]); s[1][1] = fmaf(a.y, bq.y, s[1][1]);
            s[1][2] = fmaf(a.y, bq.z, s[1][2]); s[1][3] = fmaf(a.y, bq.w, s[1][3]);
            s[2][0] = fmaf(a.z, bq.x, s[2][0]); s[2][1] = fmaf(a.z, bq.y, s[2][1]);
            s[2][2] = fmaf(a.z, bq.z, s[2][2]); s[2][3] = fmaf(a.z, bq.w, s[2][3]);
            s[3][0] = fmaf(a.w, bq.x, s[3][0]); s[3][1] = fmaf(a.w, bq.y, s[3][1]);
            s[3][2] = fmaf(a.w, bq.z, s[3][2]); s[3][3] = fmaf(a.w, bq.w, s[3][3]);
        }
#pragma unroll
        for (int i = 0; i < 4; i++) {
            float4 sv;
            sv.x = s[i][0] * inv_norm;
            sv.y = s[i][1] * inv_norm;
            sv.z = s[i][2] * inv_norm;
            sv.w = s[i][3] * inv_norm;
            *(float4*)(ss + (ty * 4 + i) * TPOS + tx * 4) = sv;
        }
        __syncthreads();

#pragma unroll
        for (int rr = 0; rr < 8; rr++) {
            int row = wid * 8 + rr;
            float v0 = ss[row * TPOS + lane];
            float v1 = ss[row * TPOS + 32 + lane];
            float mx = fmaxf(v0, v1);
#pragma unroll
            for (int off = 16; off > 0; off >>= 1)
                mx = fmaxf(mx, __shfl_xor_sync(0xffffffffu, mx, off));
            float m_old = m_s[row];
            float m_new = fmaxf(m_old, mx);
            float p0 = __expf(v0 - m_new);
            float p1 = __expf(v1 - m_new);
            ss[row * TPOS + lane] = p0;
            ss[row * TPOS + 32 + lane] = p1;
            float sum = p0 + p1;
#pragma unroll
            for (int off = 16; off > 0; off >>= 1)
                sum += __shfl_xor_sync(0xffffffffu, sum, off);
            if (lane == 0) {
                float f = __expf(m_old - m_new);
                l_s[row] = l_s[row] * f + sum;
                m_s[row] = m_new;
                f_s[row] = f;
            }
        }
        __syncthreads();

        {
            float f0 = f_s[ty * 4 + 0];
            float f1 = f_s[ty * 4 + 1];
            float f2 = f_s[ty * 4 + 2];
            float f3 = f_s[ty * 4 + 3];
#pragma unroll
            for (int j = 0; j < 8; j++) {
                accv[0][j] *= f0;
                accv[1][j] *= f1;
                accv[2][j] *= f2;
                accv[3][j] *= f3;
            }
        }
#pragma unroll 4
        for (int kk = 0; kk < 64; kk++) {
            float p0 = ss[(ty * 4 + 0) * TPOS + kk];
            float p1 = ss[(ty * 4 + 1) * TPOS + kk];
            float p2 = ss[(ty * 4 + 2) * TPOS + kk];
            float p3 = ss[(ty * 4 + 3) * TPOS + kk];
            float4 v0 = *(const float4*)(vs + kk * 128 + tx * 8);
            float4 v1 = *(const float4*)(vs + kk * 128 + tx * 8 + 4);
            accv[0][0] = fmaf(p0, v0.x, accv[0][0]); accv[0][1] = fmaf(p0, v0.y, accv[0][1]);
            accv[0][2] = fmaf(p0, v0.z, accv[0][2]); accv[0][3] = fmaf(p0, v0.w, accv[0][3]);
            accv[0][4] = fmaf(p0, v1.x, accv[0][4]); accv[0][5] = fmaf(p0, v1.y, accv[0][5]);
            accv[0][6] = fmaf(p0, v1.z, accv[0][6]); accv[0][7] = fmaf(p0, v1.w, accv[0][7]);
            accv[1][0] = fmaf(p1, v0.x, accv[1][0]); accv[1][1] = fmaf(p1, v0.y, accv[1][1]);
            accv[1][2] = fmaf(p1, v0.z, accv[1][2]); accv[1][3] = fmaf(p1, v0.w, accv[1][3]);
            accv[1][4] = fmaf(p1, v1.x, accv[1][4]); accv[1][5] = fmaf(p1, v1.y, accv[1][5]);
            accv[1][6] = fmaf(p1, v1.z, accv[1][6]); accv[1][7] = fmaf(p1, v1.w, accv[1][7]);
            accv[2][0] = fmaf(p2, v0.x, accv[2][0]); accv[2][1] = fmaf(p2, v0.y, accv[2][1]);
            accv[2][2] = fmaf(p2, v0.z, accv[2][2]); accv[2][3] = fmaf(p2, v0.w, accv[2][3]);
            accv[2][4] = fmaf(p2, v1.x, accv[2][4]); accv[2][5] = fmaf(p2, v1.y, accv[2][5]);
            accv[2][6] = fmaf(p2, v1.z, accv[2][6]); accv[2][7] = fmaf(p2, v1.w, accv[2][7]);
            accv[3][0] = fmaf(p3, v0.x, accv[3][0]); accv[3][1] = fmaf(p3, v0.y, accv[3][1]);
            accv[3][2] = fmaf(p3, v0.z, accv[3][2]); accv[3][3] = fmaf(p3, v0.w, accv[3][3]);
            accv[3][4] = fmaf(p3, v1.x, accv[3][4]); accv[3][5] = fmaf(p3, v1.y, accv[3][5]);
            accv[3][6] = fmaf(p3, v1.z, accv[3][6]); accv[3][7] = fmaf(p3, v1.w, accv[3][7]);
        }
        __syncthreads();
    }

#pragma unroll
    for (int i = 0; i < 4; i++) {
        float linv = 1.0f / l_s[ty * 4 + i];
        float* optr = O + (size_t)(b * SEQ + q0 + ty * 4 + i) * HIDDEN + h * HEAD_DIM + tx * 8;
        float4 o0, o1;
        o0.x = accv[i][0] * linv; o0.y = accv[i][1] * linv;
        o0.z = accv[i][2] * linv; o0.w = accv[i][3] * linv;
        o1.x = accv[i][4] * linv; o1.y = accv[i][5] * linv;
        o1.z = accv[i][6] * linv; o1.w = accv[i][7] * linv;
        *(float4*)optr = o0;
        *(float4*)(optr + 4) = o1;
    }
}

// ---------------- launch ----------------
extern "C" void kernel_launch(void* const* d_in, const int* in_sizes, int n_in,
                              void* d_out, int out_size) {
    (void)in_sizes; (void)n_in; (void)out_size;
    const float* x  = (const float*)d_in[0];
    const float* wq = (const float*)d_in[1];
    const float* wk = (const float*)d_in[2];
    const float* wv = (const float*)d_in[3];
    const float* wo = (const float*)d_in[4];
    float* out = (float*)d_out;

    float *qb, *kb, *vb, *ab;
    cudaGetSymbolAddress((void**)&qb, g_q);
    cudaGetSymbolAddress((void**)&kb, g_k);
    cudaGetSymbolAddress((void**)&vb, g_v);
    cudaGetSymbolAddress((void**)&ab, g_att);

    const int smem_attn = (128 * TPOS + 128 * TPOS + 64 * 128 + 64 * TPOS + 3 * 64)
                          * (int)sizeof(float);
    static int configured = 0;
    if (!configured) {
        cudaFuncSetAttribute(attn_kernel, cudaFuncAttributeMaxDynamicSharedMemorySize,
                             smem_attn);
        cudaFuncSetAttribute(gemm_mma, cudaFuncAttributeMaxDynamicSharedMemorySize,
                             G_SMEM);
        configured = 1;
    }

    dim3 blk(256);
    gemm_mma<<<dim3(HIDDEN / BN, MROWS / BM), blk, G_SMEM>>>(x, wq, qb, MROWS, HIDDEN, HIDDEN);
    gemm_mma<<<dim3(HEAD_DIM / BN, MROWS / BM), blk, G_SMEM>>>(x, wk, kb, MROWS, HEAD_DIM, HIDDEN);
    gemm_mma<<<dim3(HEAD_DIM / BN, MROWS / BM), blk, G_SMEM>>>(x, wv, vb, MROWS, HEAD_DIM, HIDDEN);
    attn_kernel<<<dim3(SEQ / 64, HEADS, BATCH), blk, smem_attn>>>(qb, kb, vb, ab);
    gemm_mma<<<dim3(HIDDEN / BN, MROWS / BM), blk, G_SMEM>>>(ab, wo, out, MROWS, HIDDEN, HIDDEN);
}

// round 8
// speedup vs baseline: 2.7741x; 2.7741x over previous
#include <cuda_runtime.h>
#include <cstdint>

#define HIDDEN 2048
#define HEADS 16
#define HEAD_DIM 128
#define BATCH 2
#define SEQ 2048
#define MROWS (BATCH * SEQ)  // 4096

// ---------------- scratch (no allocations allowed) ----------------
__device__ float g_q[MROWS * HIDDEN];     // 32 MB
__device__ float g_k[MROWS * HEAD_DIM];   // 2 MB
__device__ float g_v[MROWS * HEAD_DIM];   // 2 MB
__device__ float g_att[MROWS * HIDDEN];   // 32 MB

__device__ __forceinline__ uint32_t f2tf32(float x) {
    uint32_t r;
    asm("cvt.rna.tf32.f32 %0, %1;" : "=r"(r) : "f"(x));
    return r;
}
__device__ __forceinline__ float f2tf32f(float x) {
    return __uint_as_float(f2tf32(x));
}

#define MMA_TF32(d, a, b)                                                          \
    asm volatile(                                                                  \
        "mma.sync.aligned.m16n8k8.row.col.f32.tf32.tf32.f32 "                      \
        "{%0,%1,%2,%3}, {%4,%5,%6,%7}, {%8,%9}, {%0,%1,%2,%3};"                    \
        : "+f"((d)[0]), "+f"((d)[1]), "+f"((d)[2]), "+f"((d)[3])                   \
        : "r"((a)[0]), "r"((a)[1]), "r"((a)[2]), "r"((a)[3]),                      \
          "r"((b)[0]), "r"((b)[1]))

// ---------------- tf32 mma.sync GEMM: C[M,N] = A[M,K] @ B[N,K]^T ----------------
#define BM 128
#define BN 128
#define BK 32
#define SA 36
#define BUF_WORDS (BM * SA)
#define G_SMEM (2 * 2 * BUF_WORDS * 4)

__global__ void __launch_bounds__(256) gemm_mma(const float* __restrict__ A,
                                                const float* __restrict__ B,
                                                float* __restrict__ C,
                                                int M, int N, int K) {
    extern __shared__ float sm[];
    const int tid = threadIdx.x;
    const int w = tid >> 5;
    const int lane = tid & 31;
    const int g = lane >> 2;
    const int tg = lane & 3;
    const int warp_m = (w & 3) * 32;
    const int warp_n = (w >> 2) * 64;
    const int m0 = blockIdx.y * BM;
    const int n0 = blockIdx.x * BN;

    float acc[2][8][4];
#pragma unroll
    for (int t = 0; t < 2; t++)
#pragma unroll
        for (int u = 0; u < 8; u++)
#pragma unroll
            for (int j = 0; j < 4; j++) acc[t][u][j] = 0.0f;

    const int steps = K / BK;
    const int r_ld = tid >> 3;
    const int c_ld = (tid & 7) * 4;

    float4 afr[4], bfr[4];

    auto ldg = [&](int s) {
        const int k0 = s * BK;
#pragma unroll
        for (int i = 0; i < 4; i++) {
            int r = r_ld + i * 32;
            afr[i] = *(const float4*)(A + (size_t)(m0 + r) * K + k0 + c_ld);
            bfr[i] = *(const float4*)(B + (size_t)(n0 + r) * K + k0 + c_ld);
        }
    };
    auto sts = [&](int buf) {
        float* As = sm + buf * (2 * BUF_WORDS);
        float* Bs = As + BUF_WORDS;
#pragma unroll
        for (int i = 0; i < 4; i++) {
            int r = r_ld + i * 32;
            uint4 u;
            u.x = f2tf32(afr[i].x); u.y = f2tf32(afr[i].y);
            u.z = f2tf32(afr[i].z); u.w = f2tf32(afr[i].w);
            *(uint4*)(As + r * SA + c_ld) = u;
            u.x = f2tf32(bfr[i].x); u.y = f2tf32(bfr[i].y);
            u.z = f2tf32(bfr[i].z); u.w = f2tf32(bfr[i].w);
            *(uint4*)(Bs + r * SA + c_ld) = u;
        }
    };
    auto compute = [&](int buf) {
        const uint32_t* As = (const uint32_t*)(sm + buf * (2 * BUF_WORDS));
        const uint32_t* Bs = As + BUF_WORDS;
#pragma unroll
        for (int ks = 0; ks < 4; ks++) {
            const int kc = ks * 8 + tg;
            uint32_t a[2][4];
#pragma unroll
            for (int t = 0; t < 2; t++) {
                int row = warp_m + t * 16 + g;
                a[t][0] = As[row * SA + kc];
                a[t][1] = As[(row + 8) * SA + kc];
                a[t][2] = As[row * SA + kc + 4];
                a[t][3] = As[(row + 8) * SA + kc + 4];
            }
            uint32_t b[8][2];
#pragma unroll
            for (int u = 0; u < 8; u++) {
                int row = warp_n + u * 8 + g;
                b[u][0] = Bs[row * SA + kc];
                b[u][1] = Bs[row * SA + kc + 4];
            }
#pragma unroll
            for (int t = 0; t < 2; t++)
#pragma unroll
                for (int u = 0; u < 8; u++)
                    MMA_TF32(acc[t][u], a[t], b[u]);
        }
    };

    ldg(0);
    sts(0);
    __syncthreads();

    for (int s = 0; s < steps; s++) {
        const int cur = s & 1;
        if (s + 1 < steps) ldg(s + 1);
        compute(cur);
        if (s + 1 < steps) sts(cur ^ 1);
        __syncthreads();
    }

#pragma unroll
    for (int t = 0; t < 2; t++) {
        int r0 = m0 + warp_m + t * 16 + g;
#pragma unroll
        for (int u = 0; u < 8; u++) {
            int col = n0 + warp_n + u * 8 + 2 * tg;
            float2 v0 = make_float2(acc[t][u][0], acc[t][u][1]);
            float2 v1 = make_float2(acc[t][u][2], acc[t][u][3]);
            *(float2*)(C + (size_t)r0 * N + col) = v0;
            *(float2*)(C + (size_t)(r0 + 8) * N + col) = v1;
        }
    }
}

// ---------------- Flash attention: tf32 mma.sync QK + PV ----------------
// 64 queries/CTA, 64-key tiles, 256 threads (8 warps).
// QK: 4x2 warp grid (warp = 16x32 of S). PV: 4x2 (warp = 16x64 of O).
// smem strides: Q/K 132, V^T 68, S 66 -> conflict-free fragment LDS.
#define QS_ST 132
#define VT_ST 68
#define SS_ST 66
// float offsets in dynamic smem
#define OFF_QS 0
#define OFF_KS (64 * QS_ST)                    // 8448
#define OFF_VT (OFF_KS + 64 * QS_ST)           // 16896
#define OFF_SS (OFF_VT + 128 * VT_ST)          // 25600
#define OFF_M  (OFF_SS + 64 * SS_ST)           // 29824
#define OFF_L  (OFF_M + 64)
#define OFF_F  (OFF_L + 64)
#define A_SMEM ((OFF_F + 64) * 4)              // 120064 bytes

__global__ void __launch_bounds__(256) attn_kernel(const float* __restrict__ Q,
                                                   const float* __restrict__ Km,
                                                   const float* __restrict__ Vm,
                                                   float* __restrict__ O) {
    const int b = blockIdx.z;
    const int h = blockIdx.y;
    const int q0 = blockIdx.x * 64;

    extern __shared__ float sm[];
    float* qs  = sm + OFF_QS;
    float* ks  = sm + OFF_KS;
    float* vst = sm + OFF_VT;
    float* ss  = sm + OFF_SS;
    float* m_s = sm + OFF_M;
    float* l_s = sm + OFF_L;
    float* f_s = sm + OFF_F;

    const int tid = threadIdx.x;
    const int w = tid >> 5;
    const int lane = tid & 31;
    const int g = lane >> 2;
    const int tg = lane & 3;
    const int wm = w & 3;          // 0..3: rows wm*16..+15
    const int wn = w >> 2;         // 0..1
    const float inv_norm = 0.08838834764831845f;  // 1/sqrt(128)

    // ---- stage Q (64x128, tf32) ----
    {
        const float* qbase = Q + (size_t)(b * SEQ + q0) * HIDDEN + h * HEAD_DIM;
#pragma unroll
        for (int it = 0; it < 8; it++) {
            int i = tid + it * 256;
            int r = i >> 5;
            int c4 = (i & 31) * 4;
            float4 v = *(const float4*)(qbase + (size_t)r * HIDDEN + c4);
            float* d = qs + r * QS_ST + c4;
            d[0] = f2tf32f(v.x); d[1] = f2tf32f(v.y);
            d[2] = f2tf32f(v.z); d[3] = f2tf32f(v.w);
        }
    }
    if (tid < 64) {
        m_s[tid] = -3.0e38f;
        l_s[tid] = 0.0f;
    }

    // O accumulators: warp rows wm*16+{g,g+8}, dims wn*64 + u*8 + {2tg,2tg+1}
    float o[8][4];
#pragma unroll
    for (int u = 0; u < 8; u++)
#pragma unroll
        for (int j = 0; j < 4; j++) o[u][j] = 0.0f;

    __syncthreads();

    for (int t0 = 0; t0 < SEQ; t0 += 64) {
        // ---- stage K (row-major, tf32) and V^T ([dim][key], tf32) ----
        {
            const float* kbase = Km + (size_t)(b * SEQ + t0) * HEAD_DIM;
#pragma unroll
            for (int it = 0; it < 8; it++) {
                int i = tid + it * 256;
                int r = i >> 5;
                int c4 = (i & 31) * 4;
                float4 v = *(const float4*)(kbase + (size_t)r * HEAD_DIM + c4);
                float* d = ks + r * QS_ST + c4;
                d[0] = f2tf32f(v.x); d[1] = f2tf32f(v.y);
                d[2] = f2tf32f(v.z); d[3] = f2tf32f(v.w);
            }
            const float* vbase = Vm + (size_t)(b * SEQ + t0) * HEAD_DIM;
#pragma unroll
            for (int it = 0; it < 32; it++) {
                int i = tid + it * 256;
                int r = i >> 7;        // key 0..63
                int c = i & 127;       // dim
                vst[c * VT_ST + r] = f2tf32f(vbase[(size_t)r * HEAD_DIM + c]);
            }
        }
        __syncthreads();

        // ---- QK^T: warp computes S[wm*16..+15][wn*32..+31] (4 n-tiles) ----
        float s[4][4];
#pragma unroll
        for (int u = 0; u < 4; u++)
#pragma unroll
            for (int j = 0; j < 4; j++) s[u][j] = 0.0f;

        {
            const uint32_t* qsu = (const uint32_t*)qs;
            const uint32_t* ksu = (const uint32_t*)ks;
            const int rowa = wm * 16 + g;
            const int ncol0 = wn * 32;
#pragma unroll
            for (int kb = 0; kb < 16; kb++) {
                const int kc = kb * 8 + tg;
                uint32_t a[4];
                a[0] = qsu[rowa * QS_ST + kc];
                a[1] = qsu[(rowa + 8) * QS_ST + kc];
                a[2] = qsu[rowa * QS_ST + kc + 4];
                a[3] = qsu[(rowa + 8) * QS_ST + kc + 4];
#pragma unroll
                for (int u = 0; u < 4; u++) {
                    uint32_t bfr[2];
                    int krow = ncol0 + u * 8 + g;
                    bfr[0] = ksu[krow * QS_ST + kc];
                    bfr[1] = ksu[krow * QS_ST + kc + 4];
                    MMA_TF32(s[u], a, bfr);
                }
            }
        }
        // store scaled scores to ss (fp32)
        {
            const int rowa = wm * 16 + g;
            const int ncol0 = wn * 32 + 2 * tg;
#pragma unroll
            for (int u = 0; u < 4; u++) {
                *(float2*)(ss + rowa * SS_ST + ncol0 + u * 8) =
                    make_float2(s[u][0] * inv_norm, s[u][1] * inv_norm);
                *(float2*)(ss + (rowa + 8) * SS_ST + ncol0 + u * 8) =
                    make_float2(s[u][2] * inv_norm, s[u][3] * inv_norm);
            }
        }
        __syncthreads();

        // ---- online softmax (warp w owns rows w*8..+7); exp'd P stored tf32 ----
#pragma unroll
        for (int rr = 0; rr < 8; rr++) {
            int row = w * 8 + rr;
            float v0 = ss[row * SS_ST + lane];
            float v1 = ss[row * SS_ST + 32 + lane];
            float mx = fmaxf(v0, v1);
#pragma unroll
            for (int off = 16; off > 0; off >>= 1)
                mx = fmaxf(mx, __shfl_xor_sync(0xffffffffu, mx, off));
            float m_old = m_s[row];
            float m_new = fmaxf(m_old, mx);
            float p0 = f2tf32f(__expf(v0 - m_new));
            float p1 = f2tf32f(__expf(v1 - m_new));
            ss[row * SS_ST + lane] = p0;
            ss[row * SS_ST + 32 + lane] = p1;
            float sum = p0 + p1;
#pragma unroll
            for (int off = 16; off > 0; off >>= 1)
                sum += __shfl_xor_sync(0xffffffffu, sum, off);
            if (lane == 0) {
                float f = __expf(m_old - m_new);
                l_s[row] = l_s[row] * f + sum;
                m_s[row] = m_new;
                f_s[row] = f;
            }
        }
        __syncthreads();

        // ---- rescale O and add P @ V: warp = rows wm*16..+15, dims wn*64..+63 ----
        {
            float f0 = f_s[wm * 16 + g];
            float f1 = f_s[wm * 16 + g + 8];
#pragma unroll
            for (int u = 0; u < 8; u++) {
                o[u][0] *= f0; o[u][1] *= f0;
                o[u][2] *= f1; o[u][3] *= f1;
            }
            const uint32_t* ssu = (const uint32_t*)ss;
            const uint32_t* vtu = (const uint32_t*)vst;
            const int rowa = wm * 16 + g;
            const int dim0 = wn * 64;
#pragma unroll
            for (int kb = 0; kb < 8; kb++) {
                const int kc = kb * 8 + tg;
                uint32_t a[4];
                a[0] = ssu[rowa * SS_ST + kc];
                a[1] = ssu[(rowa + 8) * SS_ST + kc];
                a[2] = ssu[rowa * SS_ST + kc + 4];
                a[3] = ssu[(rowa + 8) * SS_ST + kc + 4];
#pragma unroll
                for (int u = 0; u < 8; u++) {
                    uint32_t bfr[2];
                    int drow = dim0 + u * 8 + g;
                    bfr[0] = vtu[drow * VT_ST + kc];
                    bfr[1] = vtu[drow * VT_ST + kc + 4];
                    MMA_TF32(o[u], a, bfr);
                }
            }
        }
        __syncthreads();
    }

    // ---- epilogue ----
    {
        const int row0 = wm * 16 + g;
        float linv0 = 1.0f / l_s[row0];
        float linv1 = 1.0f / l_s[row0 + 8];
        float* ob0 = O + (size_t)(b * SEQ + q0 + row0) * HIDDEN + h * HEAD_DIM + wn * 64 + 2 * tg;
        float* ob1 = O + (size_t)(b * SEQ + q0 + row0 + 8) * HIDDEN + h * HEAD_DIM + wn * 64 + 2 * tg;
#pragma unroll
        for (int u = 0; u < 8; u++) {
            *(float2*)(ob0 + u * 8) = make_float2(o[u][0] * linv0, o[u][1] * linv0);
            *(float2*)(ob1 + u * 8) = make_float2(o[u][2] * linv1, o[u][3] * linv1);
        }
    }
}

// ---------------- launch ----------------
extern "C" void kernel_launch(void* const* d_in, const int* in_sizes, int n_in,
                              void* d_out, int out_size) {
    (void)in_sizes; (void)n_in; (void)out_size;
    const float* x  = (const float*)d_in[0];
    const float* wq = (const float*)d_in[1];
    const float* wk = (const float*)d_in[2];
    const float* wv = (const float*)d_in[3];
    const float* wo = (const float*)d_in[4];
    float* out = (float*)d_out;

    float *qb, *kb, *vb, *ab;
    cudaGetSymbolAddress((void**)&qb, g_q);
    cudaGetSymbolAddress((void**)&kb, g_k);
    cudaGetSymbolAddress((void**)&vb, g_v);
    cudaGetSymbolAddress((void**)&ab, g_att);

    static int configured = 0;
    if (!configured) {
        cudaFuncSetAttribute(attn_kernel, cudaFuncAttributeMaxDynamicSharedMemorySize,
                             A_SMEM);
        cudaFuncSetAttribute(gemm_mma, cudaFuncAttributeMaxDynamicSharedMemorySize,
                             G_SMEM);
        configured = 1;
    }

    dim3 blk(256);
    gemm_mma<<<dim3(HIDDEN / BN, MROWS / BM), blk, G_SMEM>>>(x, wq, qb, MROWS, HIDDEN, HIDDEN);
    gemm_mma<<<dim3(HEAD_DIM / BN, MROWS / BM), blk, G_SMEM>>>(x, wk, kb, MROWS, HEAD_DIM, HIDDEN);
    gemm_mma<<<dim3(HEAD_DIM / BN, MROWS / BM), blk, G_SMEM>>>(x, wv, vb, MROWS, HEAD_DIM, HIDDEN);
    attn_kernel<<<dim3(SEQ / 64, HEADS, BATCH), blk, A_SMEM>>>(qb, kb, vb, ab);
    gemm_mma<<<dim3(HIDDEN / BN, MROWS / BM), blk, G_SMEM>>>(ab, wo, out, MROWS, HIDDEN, HIDDEN);
}